// round 16
// baseline (speedup 1.0000x reference)
#include <cuda_runtime.h>
#include <cstdint>

// ---------------- problem constants ----------------
#define BATCH_N   1048576
#define IN_SZ     64
#define HID       16
#define KDIM      80          // IN_SZ + HID
#define NDIM      80          // 5 * HID
#define TILE_M    128
#define NTHREADS  256
#define NTILES    (BATCH_N / TILE_M)   // 8192
#define GRID      456                  // 3 CTAs/SM on GB300's 152 SMs

// smem stride for A (floats): conflict-free scalar fragment LDS
#define SA 84                 // bank (20*qr + qc) % 32 all distinct over a warp

#define A_FLOATS (TILE_M * SA)        // 10752 (single buffer)
// B pairs: [kt=10][g=5][nh=2][lane=32] x float2 = 6400 floats
#define BPAIR_FLOATS 6400
#define SMEM_FLOATS (A_FLOATS + BPAIR_FLOATS + NDIM)
#define SMEM_BYTES  (SMEM_FLOATS * 4) // 68928 (~67.3 KB) -> 3 CTAs/SM

// ---------------- precomputed weights (written by prep kernel) ----------------
__device__ uint32_t g_Bp[BPAIR_FLOATS];  // tf32 B-fragment pairs, per-thread layout
__device__ float    g_bias[NDIM];

static __device__ __forceinline__ uint32_t f2tf32(float f) {
    uint32_t u;
    asm("cvt.rna.tf32.f32 %0, %1;" : "=r"(u) : "f"(f));
    return u;
}
static __device__ __forceinline__ uint32_t smem_u32(const void* p) {
    uint32_t a;
    asm("{ .reg .u64 t; cvta.to.shared.u64 t, %1; cvt.u32.u64 %0, t; }" : "=r"(a) : "l"(p));
    return a;
}

static __device__ __forceinline__ void mma_tf32(float* c, const uint32_t* a,
                                                uint32_t b0, uint32_t b1) {
    asm volatile(
        "mma.sync.aligned.m16n8k8.row.col.f32.tf32.tf32.f32 "
        "{%0,%1,%2,%3}, {%4,%5,%6,%7}, {%8,%9}, {%0,%1,%2,%3};"
        : "+f"(c[0]), "+f"(c[1]), "+f"(c[2]), "+f"(c[3])
        : "r"(a[0]), "r"(a[1]), "r"(a[2]), "r"(a[3]), "r"(b0), "r"(b1));
}

// single-instruction tanh (MUFU.TANH) — validated: rel_err unchanged vs exact
static __device__ __forceinline__ float tanh_approx(float x) {
    float y;
    asm("tanh.approx.f32 %0, %1;" : "=f"(y) : "f"(x));
    return y;
}
static __device__ __forceinline__ float softplus_fast(float x) {
    return fmaxf(x, 0.0f) + __logf(1.0f + __expf(-fabsf(x)));
}

// cp.async 16B, L1-bypassing
static __device__ __forceinline__ void cp_async16(uint32_t daddr, const void* src) {
    asm volatile("cp.async.cg.shared.global [%0], [%1], 16;" :: "r"(daddr), "l"(src));
}

// ---------------- prep: pack W into per-thread LDS.64 B-pairs + bias ----------------
// g_Bp index i: p = i&1; lane = (i>>1)&31; nh = (i>>6)&1; rest = i>>7; g = rest%5; kt = rest/5
//   qr = lane>>2, qc = lane&3
//   value = tf32( W_g[k = kt*8 + qc + 4*p][col = nh*8 + qr] )
__global__ void prep_kernel(
    const float* __restrict__ W_i, const float* __restrict__ b_i,
    const float* __restrict__ W_f, const float* __restrict__ b_f,
    const float* __restrict__ W_o, const float* __restrict__ b_o,
    const float* __restrict__ W_c, const float* __restrict__ b_c,
    const float* __restrict__ W_d, const float* __restrict__ b_d)
{
    int i = blockIdx.x * blockDim.x + threadIdx.x;
    if (i < BPAIR_FLOATS) {
        int p    = i & 1;
        int lane = (i >> 1) & 31;
        int nh   = (i >> 6) & 1;
        int rest = i >> 7;            // 0..49
        int g  = rest % 5;
        int kt = rest / 5;
        int qr = lane >> 2;
        int qc = lane & 3;
        int k   = kt * 8 + qc + 4 * p;
        int col = nh * 8 + qr;
        const float* W = (g == 0) ? W_i : (g == 1) ? W_f : (g == 2) ? W_o
                       : (g == 3) ? W_c : W_d;
        g_Bp[i] = f2tf32(W[k * HID + col]);
    } else if (i < BPAIR_FLOATS + NDIM) {
        int n = i - BPAIR_FLOATS;
        int g = n >> 4, c = n & 15;
        const float* B = (g == 0) ? b_i : (g == 1) ? b_f : (g == 2) ? b_o
                       : (g == 3) ? b_c : b_d;
        g_bias[n] = B[c];
    }
}

__global__ void __launch_bounds__(NTHREADS, 3) ctlstm_kernel(
    const float* __restrict__ x,
    const float* __restrict__ h_prev,
    const float* __restrict__ c_prev,
    const float* __restrict__ delta_t,
    float* __restrict__ out_h, float* __restrict__ out_c)
{
    extern __shared__ float smemf[];
    float*    Af = smemf;                                  // [128][SA] raw fp32
    uint32_t* Bs = reinterpret_cast<uint32_t*>(smemf + A_FLOATS);  // B pairs
    float*    bs = reinterpret_cast<float*>(Bs + BPAIR_FLOATS);    // bias[80]

    const int tid  = threadIdx.x;
    const int warp = tid >> 5;
    const int lane = tid & 31;
    const int qr   = lane >> 2;   // 0..7
    const int qc   = lane & 3;    // 0..3

    // N-split warp pairing: rg picks 32-row group, nh picks column half
    const int rg = warp & 3;
    const int nh = warp >> 2;
    const int mbase = rg * 32;
    const int j0 = nh * 8 + 2 * qc;

    // ---- one-time per CTA: B pairs + bias into smem (coalesced, L2-hot) ----
    {
        const uint4* src = reinterpret_cast<const uint4*>(g_Bp);
        uint4* dst = reinterpret_cast<uint4*>(Bs);
        #pragma unroll
        for (int it = 0; it < 7; it++) {
            int i = it * NTHREADS + tid;
            if (i < BPAIR_FLOATS / 4) dst[i] = src[i];
        }
        if (tid < NDIM) bs[tid] = g_bias[tid];
    }

    // per-thread B base: pairs at (nh*32 + lane), stride 64 float2 per (kt,g)
    const uint2* Bp2 = reinterpret_cast<const uint2*>(Bs) + nh * 32 + lane;

    for (int tile = blockIdx.x; tile < NTILES; tile += GRID) {
        const int row0 = tile * TILE_M;

        // barrier: previous tile's compute done -> safe to overwrite A (also
        // orders the one-time B copy before the first GEMM)
        __syncthreads();

        // ---- issue this tile's A fill (cp.async, L1-bypassing) ----
        // x part: 2048 float4 items, shift/mask indexing (no divisions)
        #pragma unroll
        for (int it = 0; it < 8; it++) {
            int idx = it * NTHREADS + tid;
            int m = idx >> 4;            // 0..127
            int c4 = idx & 15;           // 0..15
            cp_async16(smem_u32(Af + m * SA + c4 * 4),
                       x + (size_t)(row0 + m) * IN_SZ + c4 * 4);
        }
        // h part: 512 float4 items
        #pragma unroll
        for (int it = 0; it < 2; it++) {
            int idx = it * NTHREADS + tid;
            int m = idx >> 2;            // 0..127
            int c4 = idx & 3;            // 0..3
            cp_async16(smem_u32(Af + m * SA + IN_SZ + c4 * 4),
                       h_prev + (size_t)(row0 + m) * HID + c4 * 4);
        }
        asm volatile("cp.async.commit_group;" ::: "memory");

        // ---- epilogue operand loads overlap the async fill's DRAM latency ----
        float2 cpv[2][2];
        float  dtv[2][2];
        #pragma unroll
        for (int mt = 0; mt < 2; mt++)
            #pragma unroll
            for (int rs = 0; rs < 2; rs++) {
                size_t row = (size_t)row0 + mbase + mt * 16 + rs * 8 + qr;
                dtv[mt][rs] = delta_t[row];
                cpv[mt][rs] = *reinterpret_cast<const float2*>(c_prev + row * HID + j0);
            }

        asm volatile("cp.async.wait_group 0;" ::: "memory");
        __syncthreads();   // A tile visible to all warps

        // ---- GEMM: per warp 32 rows (2 m-tiles) x its 5 n-tiles ----
        // per kt: 8 A LDS.32 + 8 cvt + 5 B LDS.64 + 10 HMMA
        float acc[5][2][4];
        #pragma unroll
        for (int g = 0; g < 5; g++)
            #pragma unroll
            for (int mt = 0; mt < 2; mt++)
                #pragma unroll
                for (int c = 0; c < 4; c++) acc[g][mt][c] = 0.0f;

        #pragma unroll
        for (int kt = 0; kt < 10; kt++) {
            uint32_t a[2][4];
            #pragma unroll
            for (int mt = 0; mt < 2; mt++) {
                int r = mbase + mt * 16 + qr;
                int k = kt * 8 + qc;
                a[mt][0] = f2tf32(Af[r * SA + k]);
                a[mt][1] = f2tf32(Af[(r + 8) * SA + k]);
                a[mt][2] = f2tf32(Af[r * SA + k + 4]);
                a[mt][3] = f2tf32(Af[(r + 8) * SA + k + 4]);
            }
            #pragma unroll
            for (int g = 0; g < 5; g++) {
                uint2 bv = Bp2[(kt * 5 + g) * 64];
                mma_tf32(acc[g][0], a[0], bv.x, bv.y);
                mma_tf32(acc[g][1], a[1], bv.x, bv.y);
            }
        }

        // ---- epilogue: z col = g*16 + j0 + b  <- acc[g][mt][rs*2 + b] ----
        #pragma unroll
        for (int mt = 0; mt < 2; mt++) {
            #pragma unroll
            for (int rs = 0; rs < 2; rs++) {
                size_t row = (size_t)row0 + mbase + mt * 16 + rs * 8 + qr;
                float dt = dtv[mt][rs];
                float2 cp = cpv[mt][rs];
                float cpin[2] = {cp.x, cp.y};
                float h2[2], c2[2];
                #pragma unroll
                for (int b = 0; b < 2; b++) {
                    int C = j0 + b;
                    float zi = acc[0][mt][rs * 2 + b] + bs[C];
                    float zf = acc[1][mt][rs * 2 + b] + bs[16 + C];
                    float zo = acc[2][mt][rs * 2 + b] + bs[32 + C];
                    float zc = acc[3][mt][rs * 2 + b] + bs[48 + C];
                    float zd = acc[4][mt][rs * 2 + b] + bs[64 + C];
                    float ig = tanh_approx(zi);
                    float fg = tanh_approx(zf);
                    float og = tanh_approx(zo);
                    float ct = tanh_approx(zc);
                    float decay = softplus_fast(zd);
                    float cdec = cpin[b] * __expf(-decay * dt);
                    float cn = fg * cdec + ig * ct;
                    c2[b] = cn;
                    h2[b] = og * tanh_approx(cn);
                }
                *reinterpret_cast<float2*>(out_h + row * HID + j0) = make_float2(h2[0], h2[1]);
                *reinterpret_cast<float2*>(out_c + row * HID + j0) = make_float2(c2[0], c2[1]);
            }
        }
    }
}

extern "C" void kernel_launch(void* const* d_in, const int* in_sizes, int n_in,
                              void* d_out, int out_size) {
    const float* x      = (const float*)d_in[0];
    const float* h_prev = (const float*)d_in[1];
    const float* c_prev = (const float*)d_in[2];
    const float* dt     = (const float*)d_in[3];
    const float* W_i = (const float*)d_in[4];
    const float* b_i = (const float*)d_in[5];
    const float* W_f = (const float*)d_in[6];
    const float* b_f = (const float*)d_in[7];
    const float* W_o = (const float*)d_in[8];
    const float* b_o = (const float*)d_in[9];
    const float* W_c = (const float*)d_in[10];
    const float* b_c = (const float*)d_in[11];
    const float* W_d = (const float*)d_in[12];
    const float* b_d = (const float*)d_in[13];

    float* out_h = (float*)d_out;
    float* out_c = out_h + (size_t)out_size / 2;  // (h_next, c_next) concatenated

    cudaFuncSetAttribute(ctlstm_kernel, cudaFuncAttributeMaxDynamicSharedMemorySize, SMEM_BYTES);

    // one-time weight packing (cheap; graph-capturable, ordered before main)
    prep_kernel<<<(BPAIR_FLOATS + NDIM + 255) / 256, 256>>>(
        W_i, b_i, W_f, b_f, W_o, b_o, W_c, b_c, W_d, b_d);

    ctlstm_kernel<<<GRID, NTHREADS, SMEM_BYTES>>>(
        x, h_prev, c_prev, dt, out_h, out_c);
}